// round 14
// baseline (speedup 1.0000x reference)
#include <cuda_runtime.h>

#define V_NODES 2048
#define D_F     128
#define NBLK    128            // scatter blocks
#define NPB     16             // nodes per scatter block
#define NK      73             // 1 + 8 + 64 output coefficient rows
#define NOUT    (NK * D_F)     // 9344
#define ROWS_PER 4             // rows per deg block
#define RED_IBLK 37            // ceil(NOUT/256) -- out zeroing blocks

// Scratch (static device globals — no allocation allowed; zero-init at load)
__device__ float g_deg[V_NODES];               // accumulated degrees (atomic)
__device__ float g_partial[NBLK * NK * D_F];   // block-major scattering partials
__device__ int   g_ct;                         // barrier counter (monotonic across replays)

// ---------------------------------------------------------------------------
// Kernel 1: column sums of W (symmetric => column sum == row sum), directly
// accumulated into g_deg via atomicAdd (red.global.add, no return). 1024
// blocks x 256 threads; each thread sums 4 rows of its 4 columns then issues
// 4 spread atomics. g_deg is zero on entry (load init / previous scat tail).
// Blocks 0..36 also zero the output buffer (kernel boundary orders this
// before scat's atomics).
// ---------------------------------------------------------------------------
__global__ void __launch_bounds__(256) deg_part_kernel(const float* __restrict__ W,
                                                       float* __restrict__ out) {
    const int g  = blockIdx.x & 1;
    const int rc = blockIdx.x >> 1;
    const int c4 = g * 256 + threadIdx.x;          // float4 column index [0,512)

    if (blockIdx.x < RED_IBLK) {
        int i = blockIdx.x * 256 + threadIdx.x;
        if (i < NOUT) out[i] = 0.f;
    }

    const float4* base = (const float4*)W + (size_t)rc * ROWS_PER * 512 + c4;

    float4 v0 = base[0 * 512];
    float4 v1 = base[1 * 512];
    float4 v2 = base[2 * 512];
    float4 v3 = base[3 * 512];

    float ax = (v0.x + v1.x) + (v2.x + v3.x);
    float ay = (v0.y + v1.y) + (v2.y + v3.y);
    float az = (v0.z + v1.z) + (v2.z + v3.z);
    float aw = (v0.w + v1.w) + (v2.w + v3.w);

    float* dst = g_deg + 4 * c4;
    atomicAdd(dst + 0, ax);
    atomicAdd(dst + 1, ay);
    atomicAdd(dst + 2, az);
    atomicAdd(dst + 3, aw);
}

// ---------------------------------------------------------------------------
// Kernel 2: scattering + in-kernel reduce. 128 blocks x 256 threads — one
// wave (1 block/SM), so the epoch grid barrier is deadlock-free. Prologue is
// now just 16 scalar loads of the finished degrees. After the barrier the
// first 8 blocks re-zero g_deg for the next call (all prologue reads are
// complete by then), and phase B reduces the L2-hot partials into out.
// ---------------------------------------------------------------------------
__global__ void __launch_bounds__(256) scat_kernel(const float* __restrict__ f,
                                                   float* __restrict__ out) {
    __shared__ float lam_s[8][NPB];
    __shared__ float comb[NK][D_F];
    __shared__ int   s_target;

    const int b = blockIdx.x;
    const int tid = threadIdx.x;
    const int half = tid >> 7;       // 0 or 1
    const int d = tid & 127;         // feature index

    // --- prologue: direct degree read + filter responses (16 threads) ---
    if (tid < NPB) {
        float dg = g_deg[b * NPB + tid];
        float inv = 1.0f / fmaxf(1.0f, dg);       // dhalf^2 with clamp
        float E = fabsf(dg * inv);                // |eigenvalue| for this node
        float logE = logf(E);
        const float Ac = 0.34657359027997264f;    // A = 3*ln(2)/6
        float s = 1.125f;                         // (R/2)*sum(d^2) + (R/2)*d0^2
#pragma unroll
        for (int j = 2; j <= 8; j++) {
            float x = logE - Ac * (float)(j - 1) * (1.0f / 3.0f);
            float w = 0.0f;
            if (x > -Ac && x <= 0.0f)
                w = 0.5f - 0.5f * cosf(x * (6.283185307179586f / Ac));
            lam_s[j - 1][tid] = w;
            s -= w * w;
        }
        lam_s[0][tid] = sqrtf(fmaxf(s, 0.0f));    // scaling function
    }
    __syncthreads();

    // Each half handles 8 nodes x 1 feature per thread.
    const int n0 = half * 8;
    float fv[8];
#pragma unroll
    for (int n = 0; n < 8; n++)
        fv[n] = f[(size_t)(b * NPB + n0 + n) * D_F + d];

    float acc[NK];
#pragma unroll
    for (int k = 0; k < NK; k++) acc[k] = 0.f;

#pragma unroll
    for (int n = 0; n < 8; n++) {
        float v = fv[n];
        float af = fabsf(v);
        acc[0] += v;
        float l[8];
#pragma unroll
        for (int j = 0; j < 8; j++) l[j] = lam_s[j][n0 + n];   // smem broadcast
#pragma unroll
        for (int j = 0; j < 8; j++) acc[1 + j] += l[j] * af;
#pragma unroll
        for (int j1 = 0; j1 < 8; j1++) {
            float t = l[j1] * af;
#pragma unroll
            for (int j2 = 0; j2 < 8; j2++)
                acc[9 + j1 * 8 + j2] += l[j2] * t;
        }
    }

    // Combine halves through smem, half 1 stores this block's partials.
    if (half == 0) {
#pragma unroll
        for (int k = 0; k < NK; k++) comb[k][d] = acc[k];
    }
    __syncthreads();
    if (half == 1) {
        float* p = g_partial + (size_t)b * NOUT + d;
#pragma unroll
        for (int k = 0; k < NK; k++)
            p[k * D_F] = acc[k] + comb[k][d];
    }

    // ---------------- Grid barrier (128 co-resident blocks) ----------------
    __threadfence();                 // publish g_partial before arriving
    __syncthreads();
    if (tid == 0) {
        int old = atomicAdd(&g_ct, 1);
        s_target = (old / NBLK + 1) * NBLK;
    }
    __syncthreads();
    if (tid == 0) {
        while (*(volatile int*)&g_ct < s_target)
            __nanosleep(32);
    }
    __syncthreads();
    __threadfence();                 // acquire: see all blocks' partials

    // Re-zero g_deg for the next call (all prologue reads finished: every
    // block passed the barrier, and the barrier is after the prologue).
    if (b < 8) g_deg[b * 256 + tid] = 0.f;

    // ---------------- Phase B: parallel reduce ----------------
    // 2 threads per output; each sums 64 of the 128 block-partials (L2-hot).
    const int gtid = b * 256 + tid;
    if (gtid < 2 * NOUT) {
        const int i = gtid >> 1;
        const int part = gtid & 1;
        const float* p = g_partial + (size_t)part * 64 * NOUT + i;
        float s0 = 0.f, s1 = 0.f, s2 = 0.f, s3 = 0.f;
        float s4 = 0.f, s5 = 0.f, s6 = 0.f, s7 = 0.f;
#pragma unroll
        for (int k = 0; k < 64; k += 8) {
            s0 += p[(k + 0) * NOUT];
            s1 += p[(k + 1) * NOUT];
            s2 += p[(k + 2) * NOUT];
            s3 += p[(k + 3) * NOUT];
            s4 += p[(k + 4) * NOUT];
            s5 += p[(k + 5) * NOUT];
            s6 += p[(k + 6) * NOUT];
            s7 += p[(k + 7) * NOUT];
        }
        float s = (((s0 + s1) + (s2 + s3)) + ((s4 + s5) + (s6 + s7)));
        atomicAdd(out + i, s * (1.0f / (float)V_NODES));
    }
}

// ---------------------------------------------------------------------------
extern "C" void kernel_launch(void* const* d_in, const int* in_sizes, int n_in,
                              void* d_out, int out_size) {
    const float* W = (const float*)d_in[0];
    const float* f = (const float*)d_in[1];
    float* out = (float*)d_out;

    deg_part_kernel<<<1024, 256>>>(W, out);
    scat_kernel<<<NBLK, 256>>>(f, out);
}

// round 16
// speedup vs baseline: 2.6241x; 2.6241x over previous
#include <cuda_runtime.h>

#define V_NODES 2048
#define D_F     128
#define NBLK    128            // scatter blocks
#define NPB     16             // nodes per scatter block
#define NK      73             // 1 + 8 + 64 output coefficient rows
#define NOUT    (NK * D_F)     // 9344
#define RED_IBLK 37            // ceil(NOUT/256) -- out zeroing blocks
#define TILES   16             // 2048 / 128 tile bands
#define NTRI    136            // TILES*(TILES+1)/2 upper-triangle tiles

// Scratch (static device globals — no allocation allowed)
__device__ float g_rcs[TILES][TILES][128];     // band-sum table: deg_a = sum_tj g_rcs[ti][tj][r]
__device__ float g_partial[NBLK * NK * D_F];   // block-major scattering partials
__device__ int   g_ct;                         // barrier counter (monotonic across replays)

// ---------------------------------------------------------------------------
// Kernel 1: degree band-sums from the UPPER TRIANGLE of 128x128 tiles only
// (W symmetric => each tile gives row-sums for band ti and col-sums for band
// tj). 136 blocks x 512 threads; warp w handles rows w, w+16, ..., 8 rows of
// 8 coalesced LDG.128 each (batched -> MLP 8). Row-sums via shfl (a warp's 32
// lanes cover the full 128-col tile row); col partials kept in registers and
// combined through padded smem. Halves W traffic: 16.8 MB -> 8.7 MB.
// Blocks 0..36 also zero the output buffer.
// ---------------------------------------------------------------------------
__global__ void __launch_bounds__(512) deg_tile_kernel(const float* __restrict__ W,
                                                       float* __restrict__ out) {
    __shared__ float rs_sh[128];
    __shared__ float cs_sh[16][132];   // padded: stride 132 kills bank conflicts

    const int tid = threadIdx.x;
    if (blockIdx.x < RED_IBLK) {
        int i = blockIdx.x * 512 + tid;            // 37*512 > NOUT covered by blk 0..18,
        if (i < NOUT) out[i] = 0.f;                // extra blocks no-op
    }

    // map blockIdx -> (ti, tj) with ti <= tj
    int rem = blockIdx.x, ti = 0;
    while (rem >= TILES - ti) { rem -= TILES - ti; ti++; }
    const int tj = ti + rem;

    const int w = tid >> 5;          // warp [0,16)
    const int l = tid & 31;          // lane

    // tile base: rows ti*128.., cols tj*128..  (row = 512 float4)
    const float4* base = (const float4*)W + (size_t)(ti * 128) * 512 + tj * 32 + l;

    float4 v[8];
#pragma unroll
    for (int k = 0; k < 8; k++)
        v[k] = base[(size_t)(w + 16 * k) * 512];

    float cx = 0.f, cy = 0.f, cz = 0.f, cw = 0.f;  // col partials (4 cols per lane)
#pragma unroll
    for (int k = 0; k < 8; k++) {
        float4 t = v[k];
        cx += t.x; cy += t.y; cz += t.z; cw += t.w;
        float rsum = (t.x + t.y) + (t.z + t.w);
#pragma unroll
        for (int off = 16; off; off >>= 1)
            rsum += __shfl_down_sync(0xffffffffu, rsum, off);
        if (l == 0) rs_sh[w + 16 * k] = rsum;
    }
    // stash this warp's 128 col partials
    cs_sh[w][l * 4 + 0] = cx;
    cs_sh[w][l * 4 + 1] = cy;
    cs_sh[w][l * 4 + 2] = cz;
    cs_sh[w][l * 4 + 3] = cw;
    __syncthreads();

    if (tid < 128) {
        // row-sums -> band ti's contribution from band tj
        g_rcs[ti][tj][tid] = rs_sh[tid];
        if (ti != tj) {
            // col-sums -> band tj's contribution from band ti
            float s = 0.f;
#pragma unroll
            for (int k = 0; k < 16; k++)
                s += cs_sh[k][tid];
            g_rcs[tj][ti][tid] = s;
        }
    }
}

// ---------------------------------------------------------------------------
// Kernel 2: scattering + in-kernel reduce (R12 structure). 128 blocks x 256
// threads — one wave (1 block/SM), so the epoch grid barrier is deadlock-
// free. Prologue: 256 coalesced loads of the band-sum table + smem reduce.
// ---------------------------------------------------------------------------
__global__ void __launch_bounds__(256) scat_kernel(const float* __restrict__ f,
                                                   float* __restrict__ out) {
    __shared__ float lam_s[8][NPB];
    __shared__ float degp_sh[16][NPB];
    __shared__ float deg_sh[NPB];
    __shared__ float comb[NK][D_F];
    __shared__ int   s_target;

    const int b = blockIdx.x;
    const int tid = threadIdx.x;
    const int half = tid >> 7;       // 0 or 1
    const int d = tid & 127;         // feature index

    // --- degree finalize: 16 band contributions per node, fully coalesced ---
    {
        const int c  = tid & 15;             // node within tile
        const int tj = tid >> 4;             // band index [0,16)
        const int ti = b >> 3;               // 8 scat blocks per band
        const int r  = (b & 7) * 16 + c;     // row within band
        degp_sh[tj][c] = g_rcs[ti][tj][r];
    }
    __syncthreads();
    if (tid < NPB) {
        float s = 0.f;
#pragma unroll
        for (int k = 0; k < 16; k++)
            s += degp_sh[k][tid];
        deg_sh[tid] = s;
    }
    __syncthreads();

    if (tid < NPB) {
        float dg = deg_sh[tid];
        float inv = 1.0f / fmaxf(1.0f, dg);       // dhalf^2 with clamp
        float E = fabsf(dg * inv);                // |eigenvalue| for this node
        float logE = logf(E);
        const float Ac = 0.34657359027997264f;    // A = 3*ln(2)/6
        float s = 1.125f;                         // (R/2)*sum(d^2) + (R/2)*d0^2
#pragma unroll
        for (int j = 2; j <= 8; j++) {
            float x = logE - Ac * (float)(j - 1) * (1.0f / 3.0f);
            float w = 0.0f;
            if (x > -Ac && x <= 0.0f)
                w = 0.5f - 0.5f * cosf(x * (6.283185307179586f / Ac));
            lam_s[j - 1][tid] = w;
            s -= w * w;
        }
        lam_s[0][tid] = sqrtf(fmaxf(s, 0.0f));    // scaling function
    }
    __syncthreads();

    // Each half handles 8 nodes x 1 feature per thread.
    const int n0 = half * 8;
    float fv[8];
#pragma unroll
    for (int n = 0; n < 8; n++)
        fv[n] = f[(size_t)(b * NPB + n0 + n) * D_F + d];

    float acc[NK];
#pragma unroll
    for (int k = 0; k < NK; k++) acc[k] = 0.f;

#pragma unroll
    for (int n = 0; n < 8; n++) {
        float v = fv[n];
        float af = fabsf(v);
        acc[0] += v;
        float l[8];
#pragma unroll
        for (int j = 0; j < 8; j++) l[j] = lam_s[j][n0 + n];   // smem broadcast
#pragma unroll
        for (int j = 0; j < 8; j++) acc[1 + j] += l[j] * af;
#pragma unroll
        for (int j1 = 0; j1 < 8; j1++) {
            float t = l[j1] * af;
#pragma unroll
            for (int j2 = 0; j2 < 8; j2++)
                acc[9 + j1 * 8 + j2] += l[j2] * t;
        }
    }

    // Combine halves through smem, half 1 stores this block's partials.
    if (half == 0) {
#pragma unroll
        for (int k = 0; k < NK; k++) comb[k][d] = acc[k];
    }
    __syncthreads();
    if (half == 1) {
        float* p = g_partial + (size_t)b * NOUT + d;
#pragma unroll
        for (int k = 0; k < NK; k++)
            p[k * D_F] = acc[k] + comb[k][d];
    }

    // ---------------- Grid barrier (128 co-resident blocks) ----------------
    __threadfence();                 // publish g_partial before arriving
    __syncthreads();
    if (tid == 0) {
        int old = atomicAdd(&g_ct, 1);
        s_target = (old / NBLK + 1) * NBLK;
    }
    __syncthreads();
    if (tid == 0) {
        while (*(volatile int*)&g_ct < s_target)
            __nanosleep(32);
    }
    __syncthreads();
    __threadfence();                 // acquire: see all blocks' partials

    // ---------------- Phase B: parallel reduce ----------------
    // 2 threads per output; each sums 64 of the 128 block-partials (L2-hot).
    const int gtid = b * 256 + tid;
    if (gtid < 2 * NOUT) {
        const int i = gtid >> 1;
        const int part = gtid & 1;
        const float* p = g_partial + (size_t)part * 64 * NOUT + i;
        float s0 = 0.f, s1 = 0.f, s2 = 0.f, s3 = 0.f;
        float s4 = 0.f, s5 = 0.f, s6 = 0.f, s7 = 0.f;
#pragma unroll
        for (int k = 0; k < 64; k += 8) {
            s0 += p[(k + 0) * NOUT];
            s1 += p[(k + 1) * NOUT];
            s2 += p[(k + 2) * NOUT];
            s3 += p[(k + 3) * NOUT];
            s4 += p[(k + 4) * NOUT];
            s5 += p[(k + 5) * NOUT];
            s6 += p[(k + 6) * NOUT];
            s7 += p[(k + 7) * NOUT];
        }
        float s = (((s0 + s1) + (s2 + s3)) + ((s4 + s5) + (s6 + s7)));
        atomicAdd(out + i, s * (1.0f / (float)V_NODES));
    }
}

// ---------------------------------------------------------------------------
extern "C" void kernel_launch(void* const* d_in, const int* in_sizes, int n_in,
                              void* d_out, int out_size) {
    const float* W = (const float*)d_in[0];
    const float* f = (const float*)d_in[1];
    float* out = (float*)d_out;

    deg_tile_kernel<<<NTRI, 512>>>(W, out);
    scat_kernel<<<NBLK, 256>>>(f, out);
}